// round 15
// baseline (speedup 1.0000x reference)
#include <cuda_runtime.h>
#include <cuda_fp16.h>
#include <cstdint>

// ---------------------------------------------------------------- constants
#define A_DIM    2048
#define D_DIM    128
#define O_DIM    128
#define F_DIM    16
#define KBIG     (A_DIM * F_DIM)      // 32768; k = b*16 + f (contiguous in conn)
#define FILT_ROW 2080                 // 16 * 130
#define KSPLIT   18                   // ragged: 16 splits of 57 ktiles + 2 of 56
#define KT       32                   // k-depth per ktile

#define SWZ128(x) ((x) ^ (((x) >> 3) & 0x70))   // 128B rows
#define SWZ256(x) ((x) ^ (((x) >> 4) & 0xF0))   // 256B rows

// k_big smem: A16 double buffer (2x16KB) + B ring (4x8KB) + full/empty mbars
#define BIG_SMEM   (2 * 16384 + 4 * 8192 + 128)  // 65664 -> 2 CTAs/SM
#define WB_SMEM    98304

// scratch (__device__ globals: allocation-free rule)
// g_Wh TILED+SWIZZLED in 8KB tiles: tile g = k/32, within-tile byte offset
// = SWZ256((k&31)*256 + o*2) — exactly what k_big's B bulk-copy consumes.
__device__ __half g_Wh[(size_t)KBIG * O_DIM];            // 8 MB
__device__ __half g_nodeh[(size_t)A_DIM * D_DIM];        // node fp16
__device__ __half g_G[(size_t)D_DIM * A_DIM];            // G[d][f*128+o] = filt[o,f,d]
__device__ float  g_bias[32 * 128];                      // bias[fj][o] (compact)
__device__ float  g_obias[(size_t)A_DIM * O_DIM];        // bond @ bias, 1 MB
__device__ float  g_part[(size_t)KSPLIT * A_DIM * O_DIM];   // 18 MB

// ---------------------------------------------------------------- ptx utils
__device__ __forceinline__ void cpa16s(uint32_t dst, const void* src) {
    asm volatile("cp.async.cg.shared.global [%0], [%1], 16;" :: "r"(dst), "l"(src));
}
__device__ __forceinline__ void cp_commit() { asm volatile("cp.async.commit_group;"); }
__device__ __forceinline__ void cp_wait0()  { asm volatile("cp.async.wait_group 0;"); }

__device__ __forceinline__ void mbar_init(uint32_t a, uint32_t cnt) {
    asm volatile("mbarrier.init.shared.b64 [%0], %1;" :: "r"(a), "r"(cnt) : "memory");
}
__device__ __forceinline__ void mbar_expect_tx(uint32_t a, uint32_t bytes) {
    asm volatile("mbarrier.arrive.expect_tx.shared.b64 _, [%0], %1;"
                 :: "r"(a), "r"(bytes) : "memory");
}
__device__ __forceinline__ void mbar_arrive(uint32_t a) {
    asm volatile("mbarrier.arrive.shared.b64 _, [%0];" :: "r"(a) : "memory");
}
__device__ __forceinline__ void mbar_wait(uint32_t a, uint32_t parity) {
    asm volatile(
        "{\n"
        ".reg .pred P;\n"
        "LW%=:\n"
        "mbarrier.try_wait.parity.acquire.cta.shared::cta.b64 P, [%0], %1, 0x989680;\n"
        "@P bra LD%=;\n"
        "bra LW%=;\n"
        "LD%=:\n"
        "}" :: "r"(a), "r"(parity) : "memory");
}
__device__ __forceinline__ void bulk_g2s(uint32_t dst, const void* src,
                                         uint32_t bytes, uint32_t mbar) {
    asm volatile(
        "cp.async.bulk.shared::cluster.global.mbarrier::complete_tx::bytes "
        "[%0], [%1], %2, [%3];"
        :: "r"(dst), "l"(src), "r"(bytes), "r"(mbar) : "memory");
}
__device__ __forceinline__ void bar_pair(int id) {
    asm volatile("bar.sync %0, 64;" :: "r"(id) : "memory");
}

__device__ __forceinline__ void ldm_x4(uint32_t* r, uint32_t a) {
    asm volatile("ldmatrix.sync.aligned.m8n8.x4.shared.b16 {%0,%1,%2,%3}, [%4];"
        : "=r"(r[0]), "=r"(r[1]), "=r"(r[2]), "=r"(r[3]) : "r"(a));
}
__device__ __forceinline__ void ldm_x4t(uint32_t* r, uint32_t a) {
    asm volatile("ldmatrix.sync.aligned.m8n8.x4.trans.shared.b16 {%0,%1,%2,%3}, [%4];"
        : "=r"(r[0]), "=r"(r[1]), "=r"(r[2]), "=r"(r[3]) : "r"(a));
}
__device__ __forceinline__ void mma16(float* d, const uint32_t* a, const uint32_t* b) {
    asm volatile(
        "mma.sync.aligned.m16n8k16.row.col.f32.f16.f16.f32 "
        "{%0,%1,%2,%3}, {%4,%5,%6,%7}, {%8,%9}, {%0,%1,%2,%3};"
        : "+f"(d[0]), "+f"(d[1]), "+f"(d[2]), "+f"(d[3])
        : "r"(a[0]), "r"(a[1]), "r"(a[2]), "r"(a[3]), "r"(b[0]), "r"(b[1]));
}
__device__ __forceinline__ uint32_t pack_h2(float x, float y) {
    __half2 h = __floats2half2_rn(x, y);
    return *reinterpret_cast<uint32_t*>(&h);
}

// ---------------------------------------------------------------------------
// k_prep: grid 384 (R14-identical).
// ---------------------------------------------------------------------------
__global__ void __launch_bounds__(256) k_prep(const float* __restrict__ node,
                                              const float* __restrict__ filt) {
    const int t = threadIdx.x;

    if (blockIdx.x < 128) {
        __shared__ float sm[16][132];
        const int f  = blockIdx.x >> 3;
        const int oc = blockIdx.x & 7;           // o-chunk of 16
        {
            const int ol = t >> 4, seg = t & 15;
            const float* src = filt + (size_t)(oc * 16 + ol) * FILT_ROW
                                    + f * 130 + seg * 8;
            #pragma unroll
            for (int q = 0; q < 4; q++) {
                float2 v = *reinterpret_cast<const float2*>(src + q * 2);
                sm[ol][seg * 8 + q * 2]     = v.x;
                sm[ol][seg * 8 + q * 2 + 1] = v.y;
            }
        }
        if (t < 32) {
            const int o16 = t >> 1, j = t & 1, o = oc * 16 + o16;
            g_bias[(f * 2 + j) * 128 + o] =
                filt[(size_t)o * FILT_ROW + f * 130 + 128 + j];
        }
        __syncthreads();
        {
            const int o = t & 15;
            #pragma unroll
            for (int q = 0; q < 8; q++) {
                const int d = (t >> 4) * 8 + q;
                g_G[(size_t)d * A_DIM + f * 128 + oc * 16 + o] = __float2half(sm[o][d]);
            }
        }
    } else {
        const int idx = (blockIdx.x - 128) * 256 + t;   // over 65536 float4
        float4 v = reinterpret_cast<const float4*>(node)[idx];
        reinterpret_cast<uint2*>(g_nodeh)[idx] =
            make_uint2(pack_h2(v.x, v.y), pack_h2(v.z, v.w));
    }
}

// ---------------------------------------------------------------------------
// k_wbuild: grid (8, 18) — R14-identical (GEMM plane + hidden obias plane).
// ---------------------------------------------------------------------------
__global__ void __launch_bounds__(256, 1) k_wbuild(const float* __restrict__ bond) {
    extern __shared__ char smc[];
    const uint32_t sb = (uint32_t)__cvta_generic_to_shared(smc);
    const int t = threadIdx.x, lane = t & 31, wid = t >> 5;

    if (blockIdx.y >= 16) {
        float* bias_s = reinterpret_cast<float*>(smc);          // 4096 f
        float* bond_s = reinterpret_cast<float*>(smc) + 4096;   // 4096 f
        const int a0 = ((blockIdx.y - 16) * 8 + blockIdx.x) * 128;
        #pragma unroll
        for (int q = 0; q < 4; q++) {
            reinterpret_cast<float4*>(bias_s)[q * 256 + t] =
                reinterpret_cast<const float4*>(g_bias)[q * 256 + t];
            reinterpret_cast<float4*>(bond_s)[q * 256 + t] =
                reinterpret_cast<const float4*>(bond + (size_t)a0 * 32)[q * 256 + t];
        }
        __syncthreads();
        const int o = t & 127;
        const int ah = (t >> 7) * 64;
        float bcol[32];
        #pragma unroll
        for (int fj = 0; fj < 32; fj++) bcol[fj] = bias_s[fj * 128 + o];
        #pragma unroll 8
        for (int i = 0; i < 64; i++) {
            const int a = ah + i;
            float s = 0.f;
            #pragma unroll
            for (int fj = 0; fj < 32; fj++)
                s += bond_s[a * 32 + fj] * bcol[fj];
            g_obias[(size_t)(a0 + a) * O_DIM + o] = s;
        }
        return;
    }

    const int wm = wid >> 1, wn = wid & 1;
    const int b0  = blockIdx.x * 256;
    const int fo0 = blockIdx.y * 128;
    const int f   = blockIdx.y;

    #pragma unroll
    for (int q = 0; q < 16; q++) {
        int c = q * 256 + t;
        int m = c >> 4, seg = c & 15;
        cpa16s(sb + SWZ256(m * 256 + seg * 16),
               g_nodeh + (size_t)(b0 + m) * D_DIM + seg * 8);
    }
    #pragma unroll
    for (int q = 0; q < 8; q++) {
        int c = q * 256 + t;
        int d = c >> 4, seg = c & 15;
        cpa16s(sb + 65536 + SWZ256(d * 256 + seg * 16),
               g_G + (size_t)d * A_DIM + fo0 + seg * 8);
    }
    cp_commit();
    cp_wait0();
    __syncthreads();

    float acc[4][8][4];
    #pragma unroll
    for (int i = 0; i < 4; i++)
        #pragma unroll
        for (int j = 0; j < 8; j++)
            #pragma unroll
            for (int q = 0; q < 4; q++) acc[i][j][q] = 0.f;

    const int aRow = wm * 64 + (lane & 7) + ((lane >> 3) & 1) * 8;
    const int aKb  = ((lane >> 4) & 1) * 16;
    const int bK   = (lane & 7) + ((lane >> 3) & 1) * 8;
    const int bNb  = (wn * 64 + ((lane >> 4) & 1) * 8) * 2;

    #pragma unroll
    for (int kc = 0; kc < 8; kc++) {
        uint32_t a[4][4], b[4][4];
        #pragma unroll
        for (int i = 0; i < 4; i++)
            ldm_x4(a[i], sb + SWZ256((aRow + i * 16) * 256 + kc * 32 + aKb));
        #pragma unroll
        for (int jj = 0; jj < 4; jj++)
            ldm_x4t(b[jj], sb + 65536 + SWZ256((kc * 16 + bK) * 256 + bNb + jj * 32));
        #pragma unroll
        for (int i = 0; i < 4; i++)
            #pragma unroll
            for (int jj = 0; jj < 4; jj++) {
                mma16(acc[i][jj * 2],     a[i], &b[jj][0]);
                mma16(acc[i][jj * 2 + 1], a[i], &b[jj][2]);
            }
    }

    __syncthreads();
    __half* tile = reinterpret_cast<__half*>(smc);      // [256][136]
    #pragma unroll
    for (int i = 0; i < 4; i++)
        #pragma unroll
        for (int j = 0; j < 8; j++) {
            const int m = wm * 64 + i * 16 + (lane >> 2);
            const int n = wn * 64 + j * 8 + (lane & 3) * 2;
            *reinterpret_cast<uint32_t*>(tile + m * 136 + n) =
                pack_h2(acc[i][j][0], acc[i][j][1]);
            *reinterpret_cast<uint32_t*>(tile + (m + 8) * 136 + n) =
                pack_h2(acc[i][j][2], acc[i][j][3]);
        }
    __syncthreads();
    {
        const int m = t;
        const size_t k = (size_t)(b0 + m) * F_DIM + f;
        char* dst = reinterpret_cast<char*>(g_Wh) + (k >> 5) * 8192;
        const uint32_t kl = (uint32_t)(k & 31) * 256;
        const uint4* src = reinterpret_cast<const uint4*>(tile + m * 136);
        #pragma unroll
        for (int seg = 0; seg < 16; seg++)
            *reinterpret_cast<uint4*>(dst + SWZ256(kl + seg * 16)) = src[seg];
    }
}

// ---------------------------------------------------------------------------
// k_big: part[s][a,o] = sum_{k in split s} conn2d[a,k] * Wh[k,o]
// R14 structure, but the per-iteration CTA __syncthreads is replaced by a
// 64-thread named barrier per wm-pair (A data only flows within pairs), and
// B-slot reuse is guarded by empty-slot mbarriers (count 8, 1 arrive/warp).
// Warp pairs now run decoupled.
// ---------------------------------------------------------------------------
__global__ void __launch_bounds__(256, 2) k_big(const float* __restrict__ conn) {
    extern __shared__ char smc[];
    const uint32_t sb = (uint32_t)__cvta_generic_to_shared(smc);
    const int t = threadIdx.x, lane = t & 31, wid = t >> 5;
    const int wm = wid >> 1, wn = wid & 1;     // 4m x 2n, warp tile 32x64
    const int m0 = blockIdx.x * 128;
    const int sp = blockIdx.y;
    const int kt0   = (sp < 16) ? 57 * sp : 912 + 56 * (sp - 16);
    const int iters = (sp < 16) ? 57 : 56;
    const int kbase = kt0 * KT;
    const int pbar  = wm + 1;                  // named barrier id 1..4

    const uint32_t FULLB = sb + 65536;         // full[s]  at +8s
    const uint32_t EMPTB = sb + 65536 + 32;    // empty[s] at +8s
    if (t == 0) {
        #pragma unroll
        for (int s = 0; s < 4; s++) {
            mbar_init(FULLB + 8 * s, 1);
            mbar_init(EMPTB + 8 * s, 8);       // one arrive per warp
        }
    }
    __syncthreads();                            // one-time: mbar init visible

    auto issueB = [&](int n) {
        if (n < iters) {
            const int s = n & 3, j = n >> 2;
            if (j >= 1) mbar_wait(EMPTB + 8 * s, (uint32_t)(j - 1) & 1u);
            mbar_expect_tx(FULLB + 8 * s, 8192u);
            bulk_g2s(sb + 32768 + s * 8192,
                     reinterpret_cast<const char*>(g_Wh) + (size_t)(kt0 + n) * 8192,
                     8192u, FULLB + 8 * s);
        }
    };

    const int aRowG = t >> 1, aHalf = t & 1;
    const float* aSrc = conn + (size_t)(m0 + aRowG) * KBIG + kbase + aHalf * 16;
    const uint32_t aSts = aRowG * 128 + aHalf * 32;

    float4 rA[2][4];
    auto ldgA = [&](int it) {
        if (it < iters) {
            const float4* s4 = reinterpret_cast<const float4*>(aSrc + it * KT);
            #pragma unroll
            for (int q = 0; q < 4; q++) rA[it & 1][q] = s4[q];
        }
    };
    auto cvtA = [&](int it) {
        if (it < iters) {
            char* ab = smc + (it & 1) * 16384;
            const float4* r = rA[it & 1];
            #pragma unroll
            for (int q = 0; q < 4; q++)
                *reinterpret_cast<uint2*>(ab + SWZ128(aSts + q * 8)) =
                    make_uint2(pack_h2(r[q].x, r[q].y), pack_h2(r[q].z, r[q].w));
        }
    };

    if (t == 0) { issueB(0); issueB(1); issueB(2); }
    ldgA(0); ldgA(1);
    cvtA(0);
    bar_pair(pbar);                             // pair-wide: stage0 A visible

    float acc[2][8][4];
    #pragma unroll
    for (int i = 0; i < 2; i++)
        #pragma unroll
        for (int j = 0; j < 8; j++)
            #pragma unroll
            for (int q = 0; q < 4; q++) acc[i][j][q] = 0.f;

    const int aRow = wm * 32 + (lane & 7) + ((lane >> 3) & 1) * 8;
    const int aKb  = ((lane >> 4) & 1) * 16;
    const int bK   = (lane & 7) + ((lane >> 3) & 1) * 8;
    const int bNb  = (wn * 64 + ((lane >> 4) & 1) * 8) * 2;

    for (int it = 0; it < iters; ++it) {
        mbar_wait(FULLB + 8 * (it & 3), (uint32_t)(it >> 2) & 1u);
        ldgA(it + 2);

        const uint32_t ab = sb + (it & 1) * 16384;
        const uint32_t bb = sb + 32768 + (it & 3) * 8192;
        #pragma unroll
        for (int kc = 0; kc < 2; kc++) {
            uint32_t a[2][4], b[4][4];
            ldm_x4(a[0], ab + SWZ128(aRow * 128 + kc * 32 + aKb));
            ldm_x4(a[1], ab + SWZ128((aRow + 16) * 128 + kc * 32 + aKb));
            #pragma unroll
            for (int jj = 0; jj < 4; jj++)
                ldm_x4t(b[jj], bb + SWZ256((kc * 16 + bK) * 256 + bNb + jj * 32));
            #pragma unroll
            for (int i = 0; i < 2; i++)
                #pragma unroll
                for (int jj = 0; jj < 4; jj++) {
                    mma16(acc[i][jj * 2],     a[i], &b[jj][0]);
                    mma16(acc[i][jj * 2 + 1], a[i], &b[jj][2]);
                }
        }
        if (lane == 0) mbar_arrive(EMPTB + 8 * (it & 3));   // warp done with B slot
        if (t == 0) issueB(it + 3);
        cvtA(it + 1);
        bar_pair(pbar);                          // pair-wide: next A stage ready
    }

    float* dst = g_part + (size_t)sp * (A_DIM * O_DIM);
    #pragma unroll
    for (int i = 0; i < 2; i++)
        #pragma unroll
        for (int j = 0; j < 8; j++) {
            const int r0  = m0 + wm * 32 + i * 16 + (lane >> 2);
            const int col = wn * 64 + j * 8 + (lane & 3) * 2;
            *reinterpret_cast<float2*>(dst + (size_t)r0 * O_DIM + col) =
                make_float2(acc[i][j][0], acc[i][j][1]);
            *reinterpret_cast<float2*>(dst + (size_t)(r0 + 8) * O_DIM + col) =
                make_float2(acc[i][j][2], acc[i][j][3]);
        }
}

// ---------------------------------------------------------------------------
// k_reduce: out = g_obias + sum_s part[s]. Pure 19-way coalesced sum.
// ---------------------------------------------------------------------------
__global__ void __launch_bounds__(256) k_reduce(float* __restrict__ out) {
    const int idx = blockIdx.x * 256 + threadIdx.x;
    float s = g_obias[idx];
    #pragma unroll
    for (int sp = 0; sp < KSPLIT; sp++)
        s += g_part[(size_t)sp * (A_DIM * O_DIM) + idx];
    out[idx] = s;
}

// ---------------------------------------------------------------------------
extern "C" void kernel_launch(void* const* d_in, const int* in_sizes, int n_in,
                              void* d_out, int out_size) {
    const float* node = (const float*)d_in[0];   // (2048, 128)
    const float* conn = (const float*)d_in[1];   // (2048, 2048, 16)
    const float* bond = (const float*)d_in[2];   // (2048, 16, 2)
    const float* filt = (const float*)d_in[3];   // (128, 16, 130)
    float* out = (float*)d_out;                  // (2048, 128)
    (void)in_sizes; (void)n_in; (void)out_size;

    cudaFuncSetAttribute(k_wbuild, cudaFuncAttributeMaxDynamicSharedMemorySize, WB_SMEM);
    cudaFuncSetAttribute(k_big,    cudaFuncAttributeMaxDynamicSharedMemorySize, BIG_SMEM);

    k_prep<<<384, 256>>>(node, filt);
    k_wbuild<<<dim3(A_DIM / 256, 18), 256, WB_SMEM>>>(bond);
    k_big<<<dim3(A_DIM / 128, KSPLIT), 256, BIG_SMEM>>>(conn);
    k_reduce<<<1024, 256>>>(out);
}

// round 16
// speedup vs baseline: 1.0559x; 1.0559x over previous
#include <cuda_runtime.h>
#include <cuda_fp16.h>
#include <cstdint>

// ---------------------------------------------------------------- constants
#define A_DIM    2048
#define D_DIM    128
#define O_DIM    128
#define F_DIM    16
#define KBIG     (A_DIM * F_DIM)      // 32768; k = b*16 + f (contiguous in conn)
#define FILT_ROW 2080                 // 16 * 130
#define KSPLIT   18                   // ragged: 16 splits of 57 ktiles + 2 of 56
#define KT       32                   // k-depth per ktile

#define SWZ128(x) ((x) ^ (((x) >> 3) & 0x70))   // 128B rows
#define SWZ256(x) ((x) ^ (((x) >> 4) & 0xF0))   // 256B rows

// k_big smem: A16 double buffer (2x16KB) + B ring (4x8KB) + mbars
#define BIG_SMEM   (2 * 16384 + 4 * 8192 + 64)   // 65600 -> 2 CTAs/SM
#define WB_SMEM    98304

// scratch (__device__ globals: allocation-free rule)
// g_Wh TILED+SWIZZLED in 8KB tiles: tile g = k/32, within-tile byte offset
// = SWZ256((k&31)*256 + o*2) — exactly what k_big's B bulk-copy consumes.
__device__ __half g_Wh[(size_t)KBIG * O_DIM];            // 8 MB
__device__ __half g_nodeh[(size_t)A_DIM * D_DIM];        // node fp16
__device__ __half g_G[(size_t)D_DIM * A_DIM];            // G[d][f*128+o] = filt[o,f,d]
__device__ float  g_bias[32 * 128];                      // bias[fj][o] (compact)
__device__ float  g_obias[(size_t)A_DIM * O_DIM];        // bond @ bias, 1 MB
__device__ float  g_part[(size_t)KSPLIT * A_DIM * O_DIM];   // 18 MB

// ---------------------------------------------------------------- ptx utils
__device__ __forceinline__ void cpa16s(uint32_t dst, const void* src) {
    asm volatile("cp.async.cg.shared.global [%0], [%1], 16;" :: "r"(dst), "l"(src));
}
__device__ __forceinline__ void cp_commit() { asm volatile("cp.async.commit_group;"); }
__device__ __forceinline__ void cp_wait0()  { asm volatile("cp.async.wait_group 0;"); }

__device__ __forceinline__ void mbar_init(uint32_t a, uint32_t cnt) {
    asm volatile("mbarrier.init.shared.b64 [%0], %1;" :: "r"(a), "r"(cnt) : "memory");
}
__device__ __forceinline__ void mbar_expect_tx(uint32_t a, uint32_t bytes) {
    asm volatile("mbarrier.arrive.expect_tx.shared.b64 _, [%0], %1;"
                 :: "r"(a), "r"(bytes) : "memory");
}
__device__ __forceinline__ void mbar_wait(uint32_t a, uint32_t parity) {
    asm volatile(
        "{\n"
        ".reg .pred P;\n"
        "LW%=:\n"
        "mbarrier.try_wait.parity.acquire.cta.shared::cta.b64 P, [%0], %1, 0x989680;\n"
        "@P bra LD%=;\n"
        "bra LW%=;\n"
        "LD%=:\n"
        "}" :: "r"(a), "r"(parity) : "memory");
}
__device__ __forceinline__ void bulk_g2s(uint32_t dst, const void* src,
                                         uint32_t bytes, uint32_t mbar) {
    asm volatile(
        "cp.async.bulk.shared::cluster.global.mbarrier::complete_tx::bytes "
        "[%0], [%1], %2, [%3];"
        :: "r"(dst), "l"(src), "r"(bytes), "r"(mbar) : "memory");
}

__device__ __forceinline__ void ldm_x4(uint32_t* r, uint32_t a) {
    asm volatile("ldmatrix.sync.aligned.m8n8.x4.shared.b16 {%0,%1,%2,%3}, [%4];"
        : "=r"(r[0]), "=r"(r[1]), "=r"(r[2]), "=r"(r[3]) : "r"(a));
}
__device__ __forceinline__ void ldm_x4t(uint32_t* r, uint32_t a) {
    asm volatile("ldmatrix.sync.aligned.m8n8.x4.trans.shared.b16 {%0,%1,%2,%3}, [%4];"
        : "=r"(r[0]), "=r"(r[1]), "=r"(r[2]), "=r"(r[3]) : "r"(a));
}
__device__ __forceinline__ void mma16(float* d, const uint32_t* a, const uint32_t* b) {
    asm volatile(
        "mma.sync.aligned.m16n8k16.row.col.f32.f16.f16.f32 "
        "{%0,%1,%2,%3}, {%4,%5,%6,%7}, {%8,%9}, {%0,%1,%2,%3};"
        : "+f"(d[0]), "+f"(d[1]), "+f"(d[2]), "+f"(d[3])
        : "r"(a[0]), "r"(a[1]), "r"(a[2]), "r"(a[3]), "r"(b[0]), "r"(b[1]));
}
__device__ __forceinline__ uint32_t pack_h2(float x, float y) {
    __half2 h = __floats2half2_rn(x, y);
    return *reinterpret_cast<uint32_t*>(&h);
}

// ---------------------------------------------------------------------------
// k_prep: grid 384 (R14-identical).
//   Blocks 0..127:   filt transpose -> g_G + compact g_bias slice.
//   Blocks 128..383: node fp32 -> fp16 (g_nodeh).
// ---------------------------------------------------------------------------
__global__ void __launch_bounds__(256) k_prep(const float* __restrict__ node,
                                              const float* __restrict__ filt) {
    const int t = threadIdx.x;

    if (blockIdx.x < 128) {
        __shared__ float sm[16][132];
        const int f  = blockIdx.x >> 3;
        const int oc = blockIdx.x & 7;           // o-chunk of 16
        {
            const int ol = t >> 4, seg = t & 15;
            const float* src = filt + (size_t)(oc * 16 + ol) * FILT_ROW
                                    + f * 130 + seg * 8;
            #pragma unroll
            for (int q = 0; q < 4; q++) {
                float2 v = *reinterpret_cast<const float2*>(src + q * 2);
                sm[ol][seg * 8 + q * 2]     = v.x;
                sm[ol][seg * 8 + q * 2 + 1] = v.y;
            }
        }
        if (t < 32) {
            const int o16 = t >> 1, j = t & 1, o = oc * 16 + o16;
            g_bias[(f * 2 + j) * 128 + o] =
                filt[(size_t)o * FILT_ROW + f * 130 + 128 + j];
        }
        __syncthreads();
        {
            const int o = t & 15;
            #pragma unroll
            for (int q = 0; q < 8; q++) {
                const int d = (t >> 4) * 8 + q;
                g_G[(size_t)d * A_DIM + f * 128 + oc * 16 + o] = __float2half(sm[o][d]);
            }
        }
    } else {
        const int idx = (blockIdx.x - 128) * 256 + t;   // over 65536 float4
        float4 v = reinterpret_cast<const float4*>(node)[idx];
        reinterpret_cast<uint2*>(g_nodeh)[idx] =
            make_uint2(pack_h2(v.x, v.y), pack_h2(v.z, v.w));
    }
}

// ---------------------------------------------------------------------------
// k_wbuild: grid (8, 18) — R14-identical.
//   y < 16 : GEMM 2048x2048x128, CTA 256x128, 8 warps -> swizzled g_Wh.
//   y >= 16: obias blocks (hidden under the GEMM wave, 144 <= 148 SMs).
// ---------------------------------------------------------------------------
__global__ void __launch_bounds__(256, 1) k_wbuild(const float* __restrict__ bond) {
    extern __shared__ char smc[];
    const uint32_t sb = (uint32_t)__cvta_generic_to_shared(smc);
    const int t = threadIdx.x, lane = t & 31, wid = t >> 5;

    if (blockIdx.y >= 16) {
        float* bias_s = reinterpret_cast<float*>(smc);          // 4096 f
        float* bond_s = reinterpret_cast<float*>(smc) + 4096;   // 4096 f
        const int a0 = ((blockIdx.y - 16) * 8 + blockIdx.x) * 128;
        #pragma unroll
        for (int q = 0; q < 4; q++) {
            reinterpret_cast<float4*>(bias_s)[q * 256 + t] =
                reinterpret_cast<const float4*>(g_bias)[q * 256 + t];
            reinterpret_cast<float4*>(bond_s)[q * 256 + t] =
                reinterpret_cast<const float4*>(bond + (size_t)a0 * 32)[q * 256 + t];
        }
        __syncthreads();
        const int o = t & 127;
        const int ah = (t >> 7) * 64;
        float bcol[32];
        #pragma unroll
        for (int fj = 0; fj < 32; fj++) bcol[fj] = bias_s[fj * 128 + o];
        #pragma unroll 8
        for (int i = 0; i < 64; i++) {
            const int a = ah + i;
            float s = 0.f;
            #pragma unroll
            for (int fj = 0; fj < 32; fj++)
                s += bond_s[a * 32 + fj] * bcol[fj];
            g_obias[(size_t)(a0 + a) * O_DIM + o] = s;
        }
        return;
    }

    const int wm = wid >> 1, wn = wid & 1;
    const int b0  = blockIdx.x * 256;
    const int fo0 = blockIdx.y * 128;
    const int f   = blockIdx.y;

    #pragma unroll
    for (int q = 0; q < 16; q++) {
        int c = q * 256 + t;
        int m = c >> 4, seg = c & 15;
        cpa16s(sb + SWZ256(m * 256 + seg * 16),
               g_nodeh + (size_t)(b0 + m) * D_DIM + seg * 8);
    }
    #pragma unroll
    for (int q = 0; q < 8; q++) {
        int c = q * 256 + t;
        int d = c >> 4, seg = c & 15;
        cpa16s(sb + 65536 + SWZ256(d * 256 + seg * 16),
               g_G + (size_t)d * A_DIM + fo0 + seg * 8);
    }
    cp_commit();
    cp_wait0();
    __syncthreads();

    float acc[4][8][4];
    #pragma unroll
    for (int i = 0; i < 4; i++)
        #pragma unroll
        for (int j = 0; j < 8; j++)
            #pragma unroll
            for (int q = 0; q < 4; q++) acc[i][j][q] = 0.f;

    const int aRow = wm * 64 + (lane & 7) + ((lane >> 3) & 1) * 8;
    const int aKb  = ((lane >> 4) & 1) * 16;
    const int bK   = (lane & 7) + ((lane >> 3) & 1) * 8;
    const int bNb  = (wn * 64 + ((lane >> 4) & 1) * 8) * 2;

    #pragma unroll
    for (int kc = 0; kc < 8; kc++) {
        uint32_t a[4][4], b[4][4];
        #pragma unroll
        for (int i = 0; i < 4; i++)
            ldm_x4(a[i], sb + SWZ256((aRow + i * 16) * 256 + kc * 32 + aKb));
        #pragma unroll
        for (int jj = 0; jj < 4; jj++)
            ldm_x4t(b[jj], sb + 65536 + SWZ256((kc * 16 + bK) * 256 + bNb + jj * 32));
        #pragma unroll
        for (int i = 0; i < 4; i++)
            #pragma unroll
            for (int jj = 0; jj < 4; jj++) {
                mma16(acc[i][jj * 2],     a[i], &b[jj][0]);
                mma16(acc[i][jj * 2 + 1], a[i], &b[jj][2]);
            }
    }

    __syncthreads();
    __half* tile = reinterpret_cast<__half*>(smc);      // [256][136]
    #pragma unroll
    for (int i = 0; i < 4; i++)
        #pragma unroll
        for (int j = 0; j < 8; j++) {
            const int m = wm * 64 + i * 16 + (lane >> 2);
            const int n = wn * 64 + j * 8 + (lane & 3) * 2;
            *reinterpret_cast<uint32_t*>(tile + m * 136 + n) =
                pack_h2(acc[i][j][0], acc[i][j][1]);
            *reinterpret_cast<uint32_t*>(tile + (m + 8) * 136 + n) =
                pack_h2(acc[i][j][2], acc[i][j][3]);
        }
    __syncthreads();
    {
        const int m = t;                                // all 256 rows
        const size_t k = (size_t)(b0 + m) * F_DIM + f;
        char* dst = reinterpret_cast<char*>(g_Wh) + (k >> 5) * 8192;   // 8KB tiles
        const uint32_t kl = (uint32_t)(k & 31) * 256;
        const uint4* src = reinterpret_cast<const uint4*>(tile + m * 136);
        #pragma unroll
        for (int seg = 0; seg < 16; seg++)
            *reinterpret_cast<uint4*>(dst + SWZ256(kl + seg * 16)) = src[seg];
    }
}

// ---------------------------------------------------------------------------
// k_big: part[s][a,o] = sum_{k in split s} conn2d[a,k] * Wh[k,o]
// Ragged 18-way split-K (57/56 ktiles), 2 CTAs/SM, 288 CTAs = one full wave.
// Mainloop BYTE-IDENTICAL to R9/R14 (validated best). Epilogue partial
// stores use streaming policy (__stcs) so the 18MB g_part stream does not
// evict the 16x-reused g_Wh tiles from L2.
// ---------------------------------------------------------------------------
__global__ void __launch_bounds__(256, 2) k_big(const float* __restrict__ conn) {
    extern __shared__ char smc[];
    const uint32_t sb = (uint32_t)__cvta_generic_to_shared(smc);
    const int t = threadIdx.x, lane = t & 31, wid = t >> 5;
    const int wm = wid >> 1, wn = wid & 1;     // 4m x 2n, warp tile 32x64
    const int m0 = blockIdx.x * 128;
    const int sp = blockIdx.y;
    const int kt0   = (sp < 16) ? 57 * sp : 912 + 56 * (sp - 16);
    const int iters = (sp < 16) ? 57 : 56;
    const int kbase = kt0 * KT;

    const uint32_t MB = sb + 65536;            // 4 mbarriers after A+B
    if (t == 0) {
        #pragma unroll
        for (int s = 0; s < 4; s++) mbar_init(MB + 8 * s, 1);
    }
    __syncthreads();

    auto issueB = [&](int it) {
        mbar_expect_tx(MB + 8 * (it & 3), 8192u);
        bulk_g2s(sb + 32768 + (it & 3) * 8192,
                 reinterpret_cast<const char*>(g_Wh) + (size_t)(kt0 + it) * 8192,
                 8192u, MB + 8 * (it & 3));
    };

    const int aRowG = t >> 1, aHalf = t & 1;
    const float* aSrc = conn + (size_t)(m0 + aRowG) * KBIG + kbase + aHalf * 16;
    const uint32_t aSts = aRowG * 128 + aHalf * 32;

    float4 rA[2][4];
    auto ldgA = [&](int it) {
        if (it < iters) {
            const float4* s4 = reinterpret_cast<const float4*>(aSrc + it * KT);
            #pragma unroll
            for (int q = 0; q < 4; q++) rA[it & 1][q] = s4[q];
        }
    };
    auto cvtA = [&](int it) {
        if (it < iters) {
            char* ab = smc + (it & 1) * 16384;
            const float4* r = rA[it & 1];
            #pragma unroll
            for (int q = 0; q < 4; q++)
                *reinterpret_cast<uint2*>(ab + SWZ128(aSts + q * 8)) =
                    make_uint2(pack_h2(r[q].x, r[q].y), pack_h2(r[q].z, r[q].w));
        }
    };

    if (t == 0) { issueB(0); issueB(1); issueB(2); }
    ldgA(0); ldgA(1);
    cvtA(0);
    __syncthreads();

    float acc[2][8][4];
    #pragma unroll
    for (int i = 0; i < 2; i++)
        #pragma unroll
        for (int j = 0; j < 8; j++)
            #pragma unroll
            for (int q = 0; q < 4; q++) acc[i][j][q] = 0.f;

    const int aRow = wm * 32 + (lane & 7) + ((lane >> 3) & 1) * 8;
    const int aKb  = ((lane >> 4) & 1) * 16;
    const int bK   = (lane & 7) + ((lane >> 3) & 1) * 8;
    const int bNb  = (wn * 64 + ((lane >> 4) & 1) * 8) * 2;

    for (int it = 0; it < iters; ++it) {
        mbar_wait(MB + 8 * (it & 3), (uint32_t)(it >> 2) & 1u);
        ldgA(it + 2);

        const uint32_t ab = sb + (it & 1) * 16384;
        const uint32_t bb = sb + 32768 + (it & 3) * 8192;
        #pragma unroll
        for (int kc = 0; kc < 2; kc++) {
            uint32_t a[2][4], b[4][4];
            ldm_x4(a[0], ab + SWZ128(aRow * 128 + kc * 32 + aKb));
            ldm_x4(a[1], ab + SWZ128((aRow + 16) * 128 + kc * 32 + aKb));
            #pragma unroll
            for (int jj = 0; jj < 4; jj++)
                ldm_x4t(b[jj], bb + SWZ256((kc * 16 + bK) * 256 + bNb + jj * 32));
            #pragma unroll
            for (int i = 0; i < 2; i++)
                #pragma unroll
                for (int jj = 0; jj < 4; jj++) {
                    mma16(acc[i][jj * 2],     a[i], &b[jj][0]);
                    mma16(acc[i][jj * 2 + 1], a[i], &b[jj][2]);
                }
        }
        cvtA(it + 1);
        __syncthreads();
        if (t == 0 && it + 3 < iters) issueB(it + 3);
    }

    float* dst = g_part + (size_t)sp * (A_DIM * O_DIM);
    #pragma unroll
    for (int i = 0; i < 2; i++)
        #pragma unroll
        for (int j = 0; j < 8; j++) {
            const int r0  = m0 + wm * 32 + i * 16 + (lane >> 2);
            const int col = wn * 64 + j * 8 + (lane & 3) * 2;
            __stcs(reinterpret_cast<float2*>(dst + (size_t)r0 * O_DIM + col),
                   make_float2(acc[i][j][0], acc[i][j][1]));
            __stcs(reinterpret_cast<float2*>(dst + (size_t)(r0 + 8) * O_DIM + col),
                   make_float2(acc[i][j][2], acc[i][j][3]));
        }
}

// ---------------------------------------------------------------------------
// k_reduce: out = g_obias + sum_s part[s]. Pure 19-way coalesced sum,
// 1024 blocks x 256 threads; streaming loads (use-once data).
// ---------------------------------------------------------------------------
__global__ void __launch_bounds__(256) k_reduce(float* __restrict__ out) {
    const int idx = blockIdx.x * 256 + threadIdx.x;
    float s = __ldcs(&g_obias[idx]);
    #pragma unroll
    for (int sp = 0; sp < KSPLIT; sp++)
        s += __ldcs(&g_part[(size_t)sp * (A_DIM * O_DIM) + idx]);
    __stcs(&out[idx], s);
}

// ---------------------------------------------------------------------------
extern "C" void kernel_launch(void* const* d_in, const int* in_sizes, int n_in,
                              void* d_out, int out_size) {
    const float* node = (const float*)d_in[0];   // (2048, 128)
    const float* conn = (const float*)d_in[1];   // (2048, 2048, 16)
    const float* bond = (const float*)d_in[2];   // (2048, 16, 2)
    const float* filt = (const float*)d_in[3];   // (128, 16, 130)
    float* out = (float*)d_out;                  // (2048, 128)
    (void)in_sizes; (void)n_in; (void)out_size;

    cudaFuncSetAttribute(k_wbuild, cudaFuncAttributeMaxDynamicSharedMemorySize, WB_SMEM);
    cudaFuncSetAttribute(k_big,    cudaFuncAttributeMaxDynamicSharedMemorySize, BIG_SMEM);

    k_prep<<<384, 256>>>(node, filt);
    k_wbuild<<<dim3(A_DIM / 256, 18), 256, WB_SMEM>>>(bond);
    k_big<<<dim3(A_DIM / 128, KSPLIT), 256, BIG_SMEM>>>(conn);
    k_reduce<<<1024, 256>>>(out);
}

// round 17
// speedup vs baseline: 1.0977x; 1.0396x over previous
#include <cuda_runtime.h>
#include <cuda_fp16.h>
#include <cstdint>

// ---------------------------------------------------------------- constants
#define A_DIM    2048
#define D_DIM    128
#define O_DIM    128
#define F_DIM    16
#define KBIG     (A_DIM * F_DIM)      // 32768; k = b*16 + f (contiguous in conn)
#define FILT_ROW 2080                 // 16 * 130
#define KSPLIT   18                   // ragged: 16 splits of 57 ktiles + 2 of 56
#define KT       32                   // k-depth per ktile

#define SWZ128(x) ((x) ^ (((x) >> 3) & 0x70))   // 128B rows
#define SWZ256(x) ((x) ^ (((x) >> 4) & 0xF0))   // 256B rows

// k_big smem: A16 double buffer (2x16KB) + B ring (4x8KB) + mbars
#define BIG_SMEM   (2 * 16384 + 4 * 8192 + 64)   // 65600 -> 2 CTAs/SM
#define WB_SMEM    98304

// scratch (__device__ globals: allocation-free rule)
// g_Wh TILED+SWIZZLED in 8KB tiles: tile g = k/32, within-tile byte offset
// = SWZ256((k&31)*256 + o*2) — exactly what k_big's B bulk-copy consumes.
__device__ __half g_Wh[(size_t)KBIG * O_DIM];            // 8 MB
__device__ __half g_nodeh[(size_t)A_DIM * D_DIM];        // node fp16
__device__ __half g_G[(size_t)D_DIM * A_DIM];            // G[d][f*128+o] = filt[o,f,d]
__device__ float  g_bias[32 * 128];                      // bias[fj][o] (compact)
__device__ float  g_obias[(size_t)A_DIM * O_DIM];        // bond @ bias, 1 MB
__device__ float  g_part[(size_t)KSPLIT * A_DIM * O_DIM];   // 18 MB

// ---------------------------------------------------------------- ptx utils
__device__ __forceinline__ void cpa16s(uint32_t dst, const void* src) {
    asm volatile("cp.async.cg.shared.global [%0], [%1], 16;" :: "r"(dst), "l"(src));
}
__device__ __forceinline__ void cp_commit() { asm volatile("cp.async.commit_group;"); }
__device__ __forceinline__ void cp_wait0()  { asm volatile("cp.async.wait_group 0;"); }

__device__ __forceinline__ void mbar_init(uint32_t a, uint32_t cnt) {
    asm volatile("mbarrier.init.shared.b64 [%0], %1;" :: "r"(a), "r"(cnt) : "memory");
}
__device__ __forceinline__ void mbar_expect_tx(uint32_t a, uint32_t bytes) {
    asm volatile("mbarrier.arrive.expect_tx.shared.b64 _, [%0], %1;"
                 :: "r"(a), "r"(bytes) : "memory");
}
__device__ __forceinline__ void mbar_wait(uint32_t a, uint32_t parity) {
    asm volatile(
        "{\n"
        ".reg .pred P;\n"
        "LW%=:\n"
        "mbarrier.try_wait.parity.acquire.cta.shared::cta.b64 P, [%0], %1, 0x989680;\n"
        "@P bra LD%=;\n"
        "bra LW%=;\n"
        "LD%=:\n"
        "}" :: "r"(a), "r"(parity) : "memory");
}
__device__ __forceinline__ void bulk_g2s(uint32_t dst, const void* src,
                                         uint32_t bytes, uint32_t mbar) {
    asm volatile(
        "cp.async.bulk.shared::cluster.global.mbarrier::complete_tx::bytes "
        "[%0], [%1], %2, [%3];"
        :: "r"(dst), "l"(src), "r"(bytes), "r"(mbar) : "memory");
}

__device__ __forceinline__ void ldm_x4(uint32_t* r, uint32_t a) {
    asm volatile("ldmatrix.sync.aligned.m8n8.x4.shared.b16 {%0,%1,%2,%3}, [%4];"
        : "=r"(r[0]), "=r"(r[1]), "=r"(r[2]), "=r"(r[3]) : "r"(a));
}
__device__ __forceinline__ void ldm_x4t(uint32_t* r, uint32_t a) {
    asm volatile("ldmatrix.sync.aligned.m8n8.x4.trans.shared.b16 {%0,%1,%2,%3}, [%4];"
        : "=r"(r[0]), "=r"(r[1]), "=r"(r[2]), "=r"(r[3]) : "r"(a));
}
__device__ __forceinline__ void mma16(float* d, const uint32_t* a, const uint32_t* b) {
    asm volatile(
        "mma.sync.aligned.m16n8k16.row.col.f32.f16.f16.f32 "
        "{%0,%1,%2,%3}, {%4,%5,%6,%7}, {%8,%9}, {%0,%1,%2,%3};"
        : "+f"(d[0]), "+f"(d[1]), "+f"(d[2]), "+f"(d[3])
        : "r"(a[0]), "r"(a[1]), "r"(a[2]), "r"(a[3]), "r"(b[0]), "r"(b[1]));
}
__device__ __forceinline__ uint32_t pack_h2(float x, float y) {
    __half2 h = __floats2half2_rn(x, y);
    return *reinterpret_cast<uint32_t*>(&h);
}

// ---------------------------------------------------------------------------
// k_prep: grid 384 (R14-identical).
//   Blocks 0..127:   filt transpose -> g_G + compact g_bias slice.
//   Blocks 128..383: node fp32 -> fp16 (g_nodeh).
// ---------------------------------------------------------------------------
__global__ void __launch_bounds__(256) k_prep(const float* __restrict__ node,
                                              const float* __restrict__ filt) {
    const int t = threadIdx.x;

    if (blockIdx.x < 128) {
        __shared__ float sm[16][132];
        const int f  = blockIdx.x >> 3;
        const int oc = blockIdx.x & 7;           // o-chunk of 16
        {
            const int ol = t >> 4, seg = t & 15;
            const float* src = filt + (size_t)(oc * 16 + ol) * FILT_ROW
                                    + f * 130 + seg * 8;
            #pragma unroll
            for (int q = 0; q < 4; q++) {
                float2 v = *reinterpret_cast<const float2*>(src + q * 2);
                sm[ol][seg * 8 + q * 2]     = v.x;
                sm[ol][seg * 8 + q * 2 + 1] = v.y;
            }
        }
        if (t < 32) {
            const int o16 = t >> 1, j = t & 1, o = oc * 16 + o16;
            g_bias[(f * 2 + j) * 128 + o] =
                filt[(size_t)o * FILT_ROW + f * 130 + 128 + j];
        }
        __syncthreads();
        {
            const int o = t & 15;
            #pragma unroll
            for (int q = 0; q < 8; q++) {
                const int d = (t >> 4) * 8 + q;
                g_G[(size_t)d * A_DIM + f * 128 + oc * 16 + o] = __float2half(sm[o][d]);
            }
        }
    } else {
        const int idx = (blockIdx.x - 128) * 256 + t;   // over 65536 float4
        float4 v = reinterpret_cast<const float4*>(node)[idx];
        reinterpret_cast<uint2*>(g_nodeh)[idx] =
            make_uint2(pack_h2(v.x, v.y), pack_h2(v.z, v.w));
    }
}

// ---------------------------------------------------------------------------
// k_wbuild: grid (8, 18) — R14-identical.
//   y < 16 : GEMM 2048x2048x128, CTA 256x128, 8 warps -> swizzled g_Wh.
//   y >= 16: obias blocks (hidden under the GEMM wave, 144 <= 148 SMs).
// ---------------------------------------------------------------------------
__global__ void __launch_bounds__(256, 1) k_wbuild(const float* __restrict__ bond) {
    extern __shared__ char smc[];
    const uint32_t sb = (uint32_t)__cvta_generic_to_shared(smc);
    const int t = threadIdx.x, lane = t & 31, wid = t >> 5;

    if (blockIdx.y >= 16) {
        float* bias_s = reinterpret_cast<float*>(smc);          // 4096 f
        float* bond_s = reinterpret_cast<float*>(smc) + 4096;   // 4096 f
        const int a0 = ((blockIdx.y - 16) * 8 + blockIdx.x) * 128;
        #pragma unroll
        for (int q = 0; q < 4; q++) {
            reinterpret_cast<float4*>(bias_s)[q * 256 + t] =
                reinterpret_cast<const float4*>(g_bias)[q * 256 + t];
            reinterpret_cast<float4*>(bond_s)[q * 256 + t] =
                reinterpret_cast<const float4*>(bond + (size_t)a0 * 32)[q * 256 + t];
        }
        __syncthreads();
        const int o = t & 127;
        const int ah = (t >> 7) * 64;
        float bcol[32];
        #pragma unroll
        for (int fj = 0; fj < 32; fj++) bcol[fj] = bias_s[fj * 128 + o];
        #pragma unroll 8
        for (int i = 0; i < 64; i++) {
            const int a = ah + i;
            float s = 0.f;
            #pragma unroll
            for (int fj = 0; fj < 32; fj++)
                s += bond_s[a * 32 + fj] * bcol[fj];
            g_obias[(size_t)(a0 + a) * O_DIM + o] = s;
        }
        return;
    }

    const int wm = wid >> 1, wn = wid & 1;
    const int b0  = blockIdx.x * 256;
    const int fo0 = blockIdx.y * 128;
    const int f   = blockIdx.y;

    #pragma unroll
    for (int q = 0; q < 16; q++) {
        int c = q * 256 + t;
        int m = c >> 4, seg = c & 15;
        cpa16s(sb + SWZ256(m * 256 + seg * 16),
               g_nodeh + (size_t)(b0 + m) * D_DIM + seg * 8);
    }
    #pragma unroll
    for (int q = 0; q < 8; q++) {
        int c = q * 256 + t;
        int d = c >> 4, seg = c & 15;
        cpa16s(sb + 65536 + SWZ256(d * 256 + seg * 16),
               g_G + (size_t)d * A_DIM + fo0 + seg * 8);
    }
    cp_commit();
    cp_wait0();
    __syncthreads();

    float acc[4][8][4];
    #pragma unroll
    for (int i = 0; i < 4; i++)
        #pragma unroll
        for (int j = 0; j < 8; j++)
            #pragma unroll
            for (int q = 0; q < 4; q++) acc[i][j][q] = 0.f;

    const int aRow = wm * 64 + (lane & 7) + ((lane >> 3) & 1) * 8;
    const int aKb  = ((lane >> 4) & 1) * 16;
    const int bK   = (lane & 7) + ((lane >> 3) & 1) * 8;
    const int bNb  = (wn * 64 + ((lane >> 4) & 1) * 8) * 2;

    #pragma unroll
    for (int kc = 0; kc < 8; kc++) {
        uint32_t a[4][4], b[4][4];
        #pragma unroll
        for (int i = 0; i < 4; i++)
            ldm_x4(a[i], sb + SWZ256((aRow + i * 16) * 256 + kc * 32 + aKb));
        #pragma unroll
        for (int jj = 0; jj < 4; jj++)
            ldm_x4t(b[jj], sb + 65536 + SWZ256((kc * 16 + bK) * 256 + bNb + jj * 32));
        #pragma unroll
        for (int i = 0; i < 4; i++)
            #pragma unroll
            for (int jj = 0; jj < 4; jj++) {
                mma16(acc[i][jj * 2],     a[i], &b[jj][0]);
                mma16(acc[i][jj * 2 + 1], a[i], &b[jj][2]);
            }
    }

    __syncthreads();
    __half* tile = reinterpret_cast<__half*>(smc);      // [256][136]
    #pragma unroll
    for (int i = 0; i < 4; i++)
        #pragma unroll
        for (int j = 0; j < 8; j++) {
            const int m = wm * 64 + i * 16 + (lane >> 2);
            const int n = wn * 64 + j * 8 + (lane & 3) * 2;
            *reinterpret_cast<uint32_t*>(tile + m * 136 + n) =
                pack_h2(acc[i][j][0], acc[i][j][1]);
            *reinterpret_cast<uint32_t*>(tile + (m + 8) * 136 + n) =
                pack_h2(acc[i][j][2], acc[i][j][3]);
        }
    __syncthreads();
    {
        const int m = t;                                // all 256 rows
        const size_t k = (size_t)(b0 + m) * F_DIM + f;
        char* dst = reinterpret_cast<char*>(g_Wh) + (k >> 5) * 8192;   // 8KB tiles
        const uint32_t kl = (uint32_t)(k & 31) * 256;
        const uint4* src = reinterpret_cast<const uint4*>(tile + m * 136);
        #pragma unroll
        for (int seg = 0; seg < 16; seg++)
            *reinterpret_cast<uint4*>(dst + SWZ256(kl + seg * 16)) = src[seg];
    }
}

// ---------------------------------------------------------------------------
// k_big: part[s][a,o] = sum_{k in split s} conn2d[a,k] * Wh[k,o]
// Ragged 18-way split-K (57/56 ktiles), 2 CTAs/SM, 288 CTAs = one full wave.
// R14 mainloop; conn loads use __ldcs (use-once, evict-first) so the 256MB
// conn stream does not evict the 16x-reused g_Wh tiles from L2.
// g_part stores use DEFAULT policy (k_reduce wants them L2-resident).
// ---------------------------------------------------------------------------
__global__ void __launch_bounds__(256, 2) k_big(const float* __restrict__ conn) {
    extern __shared__ char smc[];
    const uint32_t sb = (uint32_t)__cvta_generic_to_shared(smc);
    const int t = threadIdx.x, lane = t & 31, wid = t >> 5;
    const int wm = wid >> 1, wn = wid & 1;     // 4m x 2n, warp tile 32x64
    const int m0 = blockIdx.x * 128;
    const int sp = blockIdx.y;
    const int kt0   = (sp < 16) ? 57 * sp : 912 + 56 * (sp - 16);
    const int iters = (sp < 16) ? 57 : 56;
    const int kbase = kt0 * KT;

    const uint32_t MB = sb + 65536;            // 4 mbarriers after A+B
    if (t == 0) {
        #pragma unroll
        for (int s = 0; s < 4; s++) mbar_init(MB + 8 * s, 1);
    }
    __syncthreads();

    auto issueB = [&](int it) {
        mbar_expect_tx(MB + 8 * (it & 3), 8192u);
        bulk_g2s(sb + 32768 + (it & 3) * 8192,
                 reinterpret_cast<const char*>(g_Wh) + (size_t)(kt0 + it) * 8192,
                 8192u, MB + 8 * (it & 3));
    };

    const int aRowG = t >> 1, aHalf = t & 1;
    const float* aSrc = conn + (size_t)(m0 + aRowG) * KBIG + kbase + aHalf * 16;
    const uint32_t aSts = aRowG * 128 + aHalf * 32;

    float4 rA[2][4];
    auto ldgA = [&](int it) {
        if (it < iters) {
            const float4* s4 = reinterpret_cast<const float4*>(aSrc + it * KT);
            #pragma unroll
            for (int q = 0; q < 4; q++) rA[it & 1][q] = __ldcs(&s4[q]);
        }
    };
    auto cvtA = [&](int it) {
        if (it < iters) {
            char* ab = smc + (it & 1) * 16384;
            const float4* r = rA[it & 1];
            #pragma unroll
            for (int q = 0; q < 4; q++)
                *reinterpret_cast<uint2*>(ab + SWZ128(aSts + q * 8)) =
                    make_uint2(pack_h2(r[q].x, r[q].y), pack_h2(r[q].z, r[q].w));
        }
    };

    if (t == 0) { issueB(0); issueB(1); issueB(2); }
    ldgA(0); ldgA(1);
    cvtA(0);
    __syncthreads();

    float acc[2][8][4];
    #pragma unroll
    for (int i = 0; i < 2; i++)
        #pragma unroll
        for (int j = 0; j < 8; j++)
            #pragma unroll
            for (int q = 0; q < 4; q++) acc[i][j][q] = 0.f;

    const int aRow = wm * 32 + (lane & 7) + ((lane >> 3) & 1) * 8;
    const int aKb  = ((lane >> 4) & 1) * 16;
    const int bK   = (lane & 7) + ((lane >> 3) & 1) * 8;
    const int bNb  = (wn * 64 + ((lane >> 4) & 1) * 8) * 2;

    for (int it = 0; it < iters; ++it) {
        mbar_wait(MB + 8 * (it & 3), (uint32_t)(it >> 2) & 1u);
        ldgA(it + 2);

        const uint32_t ab = sb + (it & 1) * 16384;
        const uint32_t bb = sb + 32768 + (it & 3) * 8192;
        #pragma unroll
        for (int kc = 0; kc < 2; kc++) {
            uint32_t a[2][4], b[4][4];
            ldm_x4(a[0], ab + SWZ128(aRow * 128 + kc * 32 + aKb));
            ldm_x4(a[1], ab + SWZ128((aRow + 16) * 128 + kc * 32 + aKb));
            #pragma unroll
            for (int jj = 0; jj < 4; jj++)
                ldm_x4t(b[jj], bb + SWZ256((kc * 16 + bK) * 256 + bNb + jj * 32));
            #pragma unroll
            for (int i = 0; i < 2; i++)
                #pragma unroll
                for (int jj = 0; jj < 4; jj++) {
                    mma16(acc[i][jj * 2],     a[i], &b[jj][0]);
                    mma16(acc[i][jj * 2 + 1], a[i], &b[jj][2]);
                }
        }
        cvtA(it + 1);
        __syncthreads();
        if (t == 0 && it + 3 < iters) issueB(it + 3);
    }

    float* dst = g_part + (size_t)sp * (A_DIM * O_DIM);
    #pragma unroll
    for (int i = 0; i < 2; i++)
        #pragma unroll
        for (int j = 0; j < 8; j++) {
            const int r0  = m0 + wm * 32 + i * 16 + (lane >> 2);
            const int col = wn * 64 + j * 8 + (lane & 3) * 2;
            *reinterpret_cast<float2*>(dst + (size_t)r0 * O_DIM + col) =
                make_float2(acc[i][j][0], acc[i][j][1]);
            *reinterpret_cast<float2*>(dst + (size_t)(r0 + 8) * O_DIM + col) =
                make_float2(acc[i][j][2], acc[i][j][3]);
        }
}

// ---------------------------------------------------------------------------
// k_reduce: out = g_obias + sum_s part[s]. Pure 19-way coalesced sum,
// 1024 blocks x 256 threads (default cache policy: partials are L2-hot).
// ---------------------------------------------------------------------------
__global__ void __launch_bounds__(256) k_reduce(float* __restrict__ out) {
    const int idx = blockIdx.x * 256 + threadIdx.x;
    float s = g_obias[idx];
    #pragma unroll
    for (int sp = 0; sp < KSPLIT; sp++)
        s += g_part[(size_t)sp * (A_DIM * O_DIM) + idx];
    out[idx] = s;
}

// ---------------------------------------------------------------------------
extern "C" void kernel_launch(void* const* d_in, const int* in_sizes, int n_in,
                              void* d_out, int out_size) {
    const float* node = (const float*)d_in[0];   // (2048, 128)
    const float* conn = (const float*)d_in[1];   // (2048, 2048, 16)
    const float* bond = (const float*)d_in[2];   // (2048, 16, 2)
    const float* filt = (const float*)d_in[3];   // (128, 16, 130)
    float* out = (float*)d_out;                  // (2048, 128)
    (void)in_sizes; (void)n_in; (void)out_size;

    cudaFuncSetAttribute(k_wbuild, cudaFuncAttributeMaxDynamicSharedMemorySize, WB_SMEM);
    cudaFuncSetAttribute(k_big,    cudaFuncAttributeMaxDynamicSharedMemorySize, BIG_SMEM);

    k_prep<<<384, 256>>>(node, filt);
    k_wbuild<<<dim3(A_DIM / 256, 18), 256, WB_SMEM>>>(bond);
    k_big<<<dim3(A_DIM / 128, KSPLIT), 256, BIG_SMEM>>>(conn);
    k_reduce<<<1024, 256>>>(out);
}